// round 11
// baseline (speedup 1.0000x reference)
#include <cuda_runtime.h>

// BucketAdjustedHinge as fused per-(bucket,segment) piecewise-linear table:
// out = W[b][j]*x + C[b][j]. Table in smem, split into two float arrays
// (W then C) so 4B gathers use all 32 banks. Persistent blocks + atomic
// work-stealing tile scheduler to kill cross-CTA completion spread.
// (Resubmit of R7 — bench infra failed; kernel audited for deadlock/replay
// determinism: prefetch atomics are fenced before g_done, reset fires last.)

#define NB 64
#define KK 20
#define TS 21                    // KK + 1 (entry 0 = below all knots)
#define TABN (NB * TS)           // 1344
#define TPB 256
#define NEXACT 4194304
#define TILE_ELEMS 1024          // 1 float4 per thread per tile
#define NT (NEXACT / TILE_ELEMS) // 4096 tiles
#define NBLOCKS (148 * 4)        // 592 persistent blocks

__device__ unsigned int g_ctr  = 0;
__device__ unsigned int g_done = 0;

__device__ __forceinline__ void build_table(
        float* tab2,             // [0..TABN) = W, [TABN..2*TABN) = C
        const float* __restrict__ base_knots,
        const float* __restrict__ base_w,
        const float* __restrict__ base_b,
        const float* __restrict__ adj_knots,
        const float* __restrict__ adj_w,
        const float* __restrict__ adj_b,
        int tid) {
    if (tid < NB) {
        const int b = tid;
        float cb   = __ldg(base_b) + __ldg(adj_b + b);
        float runW = 0.0f;
        float runC = 0.0f;
        tab2[b * TS]        = 0.0f;
        tab2[b * TS + TABN] = cb;
#pragma unroll
        for (int j = 0; j < KK; ++j) {
            float bw = __ldg(base_w + j);
            float aw = __ldg(adj_w + b * KK + j);
            runW += bw + aw;
            runC = fmaf(bw, __ldg(base_knots + j), runC);
            runC = fmaf(aw, __ldg(adj_knots + b * KK + j), runC);
            tab2[b * TS + j + 1]        = runW;
            tab2[b * TS + j + 1 + TABN] = cb - runC;
        }
    }
}

__device__ __forceinline__ float eval1(const float* tab2, float xf, int b,
                                       float ih, float c1) {
    int jp = __float2int_rd(fmaf(xf, ih, c1));   // floor((x-k0)*ih)+1 via c1
    jp = min(max(jp, 0), KK);
    int o = b * TS + jp;
    float W = tab2[o];
    float C = tab2[o + TABN];
    return fmaf(W, xf, C);
}

__device__ __forceinline__ float4 eval4(const float* tab2, float4 xv, int4 bv,
                                        float ih, float c1) {
    float4 o;
    o.x = eval1(tab2, xv.x, bv.x, ih, c1);
    o.y = eval1(tab2, xv.y, bv.y, ih, c1);
    o.z = eval1(tab2, xv.z, bv.z, ih, c1);
    o.w = eval1(tab2, xv.w, bv.w, ih, c1);
    return o;
}

__global__ void __launch_bounds__(TPB) bah_sched(
        const float4* __restrict__ x4,
        const int4*   __restrict__ b4,
        const float*  __restrict__ base_knots,
        const float*  __restrict__ base_w,
        const float*  __restrict__ base_b,
        const float*  __restrict__ adj_knots,
        const float*  __restrict__ adj_w,
        const float*  __restrict__ adj_b,
        float4*       __restrict__ out4) {
    __shared__ float tab2[2 * TABN];
    __shared__ unsigned int s_t[2];

    const int tid = threadIdx.x;
    build_table(tab2, base_knots, base_w, base_b, adj_knots, adj_w, adj_b, tid);
    const float k0 = __ldg(base_knots);
    const float ih = (float)(KK - 1) / (__ldg(base_knots + KK - 1) - k0);
    const float c1 = 1.0f - k0 * ih;

    if (tid == 0) s_t[0] = atomicAdd(&g_ctr, 1u);
    __syncthreads();

    int p = 0;
    unsigned int t = s_t[0];
    while (t < NT) {
        // prefetch next tile id (overlaps with this tile's memory work)
        if (tid == 0) s_t[p ^ 1] = atomicAdd(&g_ctr, 1u);

        const int idx = (int)t * (TILE_ELEMS / 4) + tid;   // float4 index
        float4 xv = x4[idx];
        int4   bv = b4[idx];
        out4[idx] = eval4(tab2, xv, bv, ih, c1);

        p ^= 1;
        __syncthreads();
        t = s_t[p];
    }

    // self-resetting scheduler state (deterministic across graph replays):
    // every block's g_ctr atomics precede its fenced g_done increment, and
    // only the final g_done incrementer resets, so no atomic lands post-reset.
    if (tid == 0) {
        __threadfence();
        unsigned int d = atomicAdd(&g_done, 1u);
        if (d == (unsigned int)(gridDim.x - 1)) {
            g_ctr  = 0;
            g_done = 0;
            __threadfence();
        }
    }
}

// Generic fallback: persistent grid-stride (any n), no scheduler.
__global__ void __launch_bounds__(TPB) bah_generic(
        const float*  __restrict__ x,
        const int*    __restrict__ bidx,
        const float*  __restrict__ base_knots,
        const float*  __restrict__ base_w,
        const float*  __restrict__ base_b,
        const float*  __restrict__ adj_knots,
        const float*  __restrict__ adj_w,
        const float*  __restrict__ adj_b,
        float*        __restrict__ out,
        int n) {
    __shared__ float tab2[2 * TABN];
    const int tid = threadIdx.x;
    build_table(tab2, base_knots, base_w, base_b, adj_knots, adj_w, adj_b, tid);
    const float k0 = __ldg(base_knots);
    const float ih = (float)(KK - 1) / (__ldg(base_knots + KK - 1) - k0);
    const float c1 = 1.0f - k0 * ih;
    __syncthreads();

    const int n4     = n >> 2;
    const int stride = gridDim.x * TPB;
    const float4* __restrict__ x4   = (const float4*)x;
    const int4*   __restrict__ b4   = (const int4*)bidx;
    float4*       __restrict__ out4 = (float4*)out;

    for (int idx = blockIdx.x * TPB + tid; idx < n4; idx += stride) {
        float4 xv = x4[idx];
        int4   bv = b4[idx];
        out4[idx] = eval4(tab2, xv, bv, ih, c1);
    }
    if (blockIdx.x == 0) {
        for (int i = (n4 << 2) + tid; i < n; i += TPB)
            out[i] = eval1(tab2, x[i], bidx[i], ih, c1);
    }
}

extern "C" void kernel_launch(void* const* d_in, const int* in_sizes, int n_in,
                              void* d_out, int out_size) {
    const float* x          = (const float*)d_in[0];
    const int*   bidx       = (const int*)  d_in[1];
    const float* base_knots = (const float*)d_in[2];
    const float* base_w     = (const float*)d_in[3];
    const float* base_b     = (const float*)d_in[4];
    const float* adj_knots  = (const float*)d_in[5];
    const float* adj_w      = (const float*)d_in[6];
    const float* adj_b      = (const float*)d_in[7];

    int n = in_sizes[0];

    if (n == NEXACT) {
        bah_sched<<<NBLOCKS, TPB>>>((const float4*)x, (const int4*)bidx,
                                    base_knots, base_w, base_b,
                                    adj_knots, adj_w, adj_b, (float4*)d_out);
    } else {
        int n4 = n >> 2;
        int blocks = 148 * 8;
        int needed = (n4 + TPB - 1) / TPB;
        if (needed < blocks) blocks = needed;
        if (blocks < 1) blocks = 1;
        bah_generic<<<blocks, TPB>>>(x, bidx, base_knots, base_w, base_b,
                                     adj_knots, adj_w, adj_b, (float*)d_out, n);
    }
}

// round 12
// speedup vs baseline: 1.0757x; 1.0757x over previous
#include <cuda_runtime.h>
#include <cstdint>

// BucketAdjustedHinge as fused per-(bucket,segment) piecewise-linear table:
// out = W[b][j]*x + C[b][j]. Exact kernel decouples global-load latency from
// the register scoreboard via cp.async (LDGSTS) staging: each thread stages
// its own 16B x / 16B bidx per stage into smem (4 stages fully in flight),
// consumes via short-latency LDS, stores via STG.128. No in-loop block syncs.

#define NB 64
#define KK 20
#define TS 21                    // KK + 1 (entry 0 = below all knots)
#define TABN (NB * TS)
#define TPB 256
#define NEXACT 4194304
#define EB 1024                  // exact blocks; n4 = 2^20 = EB*TPB*4
#define STAGES 4

__device__ __forceinline__ uint32_t s2u(const void* p) {
    return (uint32_t)__cvta_generic_to_shared(p);
}
__device__ __forceinline__ void cp_async16(uint32_t s, const void* g) {
    asm volatile("cp.async.cg.shared.global [%0], [%1], 16;" :: "r"(s), "l"(g));
}
__device__ __forceinline__ void cp_commit() {
    asm volatile("cp.async.commit_group;");
}
template <int P>
__device__ __forceinline__ void cp_wait() {
    asm volatile("cp.async.wait_group %0;" :: "n"(P));
}

__device__ __forceinline__ void build_table(
        float2* tab,
        const float* __restrict__ base_knots,
        const float* __restrict__ base_w,
        const float* __restrict__ base_b,
        const float* __restrict__ adj_knots,
        const float* __restrict__ adj_w,
        const float* __restrict__ adj_b,
        int tid) {
    if (tid < NB) {
        const int b = tid;
        float cb   = __ldg(base_b) + __ldg(adj_b + b);
        float runW = 0.0f;
        float runC = 0.0f;
        tab[b * TS] = make_float2(0.0f, cb);
#pragma unroll
        for (int j = 0; j < KK; ++j) {
            float bw = __ldg(base_w + j);
            float aw = __ldg(adj_w + b * KK + j);
            runW += bw + aw;
            runC = fmaf(bw, __ldg(base_knots + j), runC);
            runC = fmaf(aw, __ldg(adj_knots + b * KK + j), runC);
            tab[b * TS + j + 1] = make_float2(runW, cb - runC);
        }
    }
}

__device__ __forceinline__ float eval1(const float2* tab, float xf, int b,
                                       float ih, float c1) {
    int jp = __float2int_rd(fmaf(xf, ih, c1));   // floor((x-k0)*ih)+1 via c1
    jp = min(max(jp, 0), KK);
    float2 t = tab[b * TS + jp];
    return fmaf(t.x, xf, t.y);
}

__device__ __forceinline__ float4 eval4(const float2* tab, float4 xv, int4 bv,
                                        float ih, float c1) {
    float4 o;
    o.x = eval1(tab, xv.x, bv.x, ih, c1);
    o.y = eval1(tab, xv.y, bv.y, ih, c1);
    o.z = eval1(tab, xv.z, bv.z, ih, c1);
    o.w = eval1(tab, xv.w, bv.w, ih, c1);
    return o;
}

struct Smem {
    float2 tab[TABN];
    float4 xs[STAGES][TPB];
    int4   bs[STAGES][TPB];
};

template <int WAITP>
__device__ __forceinline__ void pipe_step(
        Smem* sm, int s, int tid, int i0, int strd,
        const float2* tab, float ih, float c1, float4* __restrict__ out4) {
    cp_wait<WAITP>();
    float4 xv = sm->xs[s][tid];
    int4   bv = sm->bs[s][tid];
    out4[i0 + s * strd] = eval4(tab, xv, bv, ih, c1);
}

__global__ void __launch_bounds__(TPB) bah_pipe(
        const float4* __restrict__ x4,
        const int4*   __restrict__ b4,
        const float*  __restrict__ base_knots,
        const float*  __restrict__ base_w,
        const float*  __restrict__ base_b,
        const float*  __restrict__ adj_knots,
        const float*  __restrict__ adj_w,
        const float*  __restrict__ adj_b,
        float4*       __restrict__ out4) {
    __shared__ Smem sm;
    const int tid = threadIdx.x;
    const int strd = EB * TPB;                 // float4 stride between tiles
    const int i0 = blockIdx.x * TPB + tid;

    // issue all 4 stages first (independent of table) — loads start ASAP
#pragma unroll
    for (int s = 0; s < STAGES; ++s) {
        cp_async16(s2u(&sm.xs[s][tid]), x4 + i0 + s * strd);
        cp_async16(s2u(&sm.bs[s][tid]), b4 + i0 + s * strd);
        cp_commit();
    }

    build_table(sm.tab, base_knots, base_w, base_b, adj_knots, adj_w, adj_b, tid);
    const float k0 = __ldg(base_knots);
    const float ih = (float)(KK - 1) / (__ldg(base_knots + KK - 1) - k0);
    const float c1 = 1.0f - k0 * ih;
    __syncthreads();                            // table visibility only

    pipe_step<3>(&sm, 0, tid, i0, strd, sm.tab, ih, c1, out4);
    pipe_step<2>(&sm, 1, tid, i0, strd, sm.tab, ih, c1, out4);
    pipe_step<1>(&sm, 2, tid, i0, strd, sm.tab, ih, c1, out4);
    pipe_step<0>(&sm, 3, tid, i0, strd, sm.tab, ih, c1, out4);
}

// Generic fallback: persistent grid-stride (any n).
__global__ void __launch_bounds__(TPB) bah_generic(
        const float*  __restrict__ x,
        const int*    __restrict__ bidx,
        const float*  __restrict__ base_knots,
        const float*  __restrict__ base_w,
        const float*  __restrict__ base_b,
        const float*  __restrict__ adj_knots,
        const float*  __restrict__ adj_w,
        const float*  __restrict__ adj_b,
        float*        __restrict__ out,
        int n) {
    __shared__ float2 tab[TABN];
    const int tid = threadIdx.x;
    build_table(tab, base_knots, base_w, base_b, adj_knots, adj_w, adj_b, tid);
    const float k0 = __ldg(base_knots);
    const float ih = (float)(KK - 1) / (__ldg(base_knots + KK - 1) - k0);
    const float c1 = 1.0f - k0 * ih;
    __syncthreads();

    const int n4     = n >> 2;
    const int stride = gridDim.x * TPB;
    const float4* __restrict__ x4   = (const float4*)x;
    const int4*   __restrict__ b4   = (const int4*)bidx;
    float4*       __restrict__ out4 = (float4*)out;

    for (int idx = blockIdx.x * TPB + tid; idx < n4; idx += stride) {
        float4 xv = x4[idx];
        int4   bv = b4[idx];
        out4[idx] = eval4(tab, xv, bv, ih, c1);
    }
    if (blockIdx.x == 0) {
        for (int i = (n4 << 2) + tid; i < n; i += TPB)
            out[i] = eval1(tab, x[i], bidx[i], ih, c1);
    }
}

extern "C" void kernel_launch(void* const* d_in, const int* in_sizes, int n_in,
                              void* d_out, int out_size) {
    const float* x          = (const float*)d_in[0];
    const int*   bidx       = (const int*)  d_in[1];
    const float* base_knots = (const float*)d_in[2];
    const float* base_w     = (const float*)d_in[3];
    const float* base_b     = (const float*)d_in[4];
    const float* adj_knots  = (const float*)d_in[5];
    const float* adj_w      = (const float*)d_in[6];
    const float* adj_b      = (const float*)d_in[7];

    int n = in_sizes[0];

    if (n == NEXACT) {
        bah_pipe<<<EB, TPB>>>((const float4*)x, (const int4*)bidx,
                              base_knots, base_w, base_b,
                              adj_knots, adj_w, adj_b, (float4*)d_out);
    } else {
        int n4 = n >> 2;
        int blocks = 148 * 8;
        int needed = (n4 + TPB - 1) / TPB;
        if (needed < blocks) blocks = needed;
        if (blocks < 1) blocks = 1;
        bah_generic<<<blocks, TPB>>>(x, bidx, base_knots, base_w, base_b,
                                     adj_knots, adj_w, adj_b, (float*)d_out, n);
    }
}